// round 9
// baseline (speedup 1.0000x reference)
#include <cuda_runtime.h>

// LinearActorNet: B=2048, K=512, N=256, T=64. task_id/action int32.
// out layout (float32): [action(B) | log_prob(B) | entropy(B)]
//
// 3-stage deterministic pipeline (no atomics):
//  1) setup:  64 CTAs x 256 thr, ballot compaction into per-task lists.
//  2) logits: grid (64 tasks x 4 slots x 4 K-quarters), 256 thr, TM=16 rows,
//     1 col/thread, packed f32x2 FFMA; partials to g_part[ks].
//  3) softmax: 256 CTAs x 8 rows; sum 4 partials + bias, fused log-softmax.

#define BB 2048
#define KK 512
#define NN 256
#define TT 64
#define TM 16
#define NSLOT 4
#define KSPLIT 4
#define KH 128
#define LSTRIDE 128

__device__ unsigned short g_list[TT * LSTRIDE];
__device__ int g_cnt[TT];
__device__ float g_part[KSPLIT][BB][NN];

union f2u { float2 f; unsigned long long u; };
__device__ __forceinline__ unsigned long long pk(float lo, float hi) {
    f2u u; u.f = make_float2(lo, hi); return u.u;
}
__device__ __forceinline__ float fold(unsigned long long v) {
    f2u u; u.u = v; return u.f.x + u.f.y;
}
#define FFMA2(d, a, b) \
    asm("fma.rn.f32x2 %0, %1, %2, %0;" : "+l"(d) : "l"(a), "l"(b))

// ---------------- setup: per-task parallel compaction ----------------
__global__ __launch_bounds__(256, 4)
void setup_kernel(const int* __restrict__ task_id)
{
    const int t    = blockIdx.x;
    const int lane = threadIdx.x & 31;
    const int w    = threadIdx.x >> 5;          // 0..7
    const unsigned lt = (1u << lane) - 1u;
    __shared__ int wcnt[8];

    // warp w covers samples [w*256, (w+1)*256)
    int c = 0;
    #pragma unroll
    for (int i = 0; i < 8; i++) {
        int idx = w * 256 + i * 32 + lane;
        c += __popc(__ballot_sync(0xffffffffu, task_id[idx] == t));
    }
    if (lane == 0) wcnt[w] = c;
    __syncthreads();
    int base = 0;
    #pragma unroll
    for (int i = 0; i < 8; i++) if (i < w) base += wcnt[i];
    if (w == 7 && lane == 0) g_cnt[t] = base + wcnt[7];

    #pragma unroll
    for (int i = 0; i < 8; i++) {
        int idx = w * 256 + i * 32 + lane;
        bool p = (task_id[idx] == t);
        unsigned m = __ballot_sync(0xffffffffu, p);
        if (p) {
            int pos = base + __popc(m & lt);
            if (pos < LSTRIDE)
                g_list[t * LSTRIDE + pos] = (unsigned short)idx;
        }
        base += __popc(m);
    }
}

// ---------------- stage 1: split-K partial logits ----------------
__global__ __launch_bounds__(256, 4)
void logits_kernel(const float* __restrict__ xs,
                   const float* __restrict__ W)
{
    __shared__ float xs_s[TM][KH];          // 8 KB

    const int tid  = threadIdx.x;           // output column n = tid
    const int t    = blockIdx.x;
    const int slot = blockIdx.y;
    const int ks   = blockIdx.z;

    const int cnt = min(g_cnt[t], LSTRIDE);
    if (slot * TM >= cnt) return;
    const unsigned short* __restrict__ lst = g_list + t * LSTRIDE;

    const float* __restrict__ Wt =
        W + (size_t)t * (KK * NN) + (size_t)ks * KH * NN + tid;

    for (int tile = slot; tile * TM < cnt; tile += NSLOT) {
        const int m0 = tile * TM;
        const int mc = min(TM, cnt - m0);
        __syncthreads();

        // ---- stage xs tile [TM][KH] (float4, coalesced) ----
        #pragma unroll
        for (int i = 0; i < (TM * KH / 4) / 256; i++) {   // 2 iters
            int idx = i * 256 + tid;
            int m = idx >> 5;                             // 32 float4 per row
            int c = idx & 31;
            float4 v = make_float4(0.f, 0.f, 0.f, 0.f);
            if (m < mc) {
                const float4* src =
                    (const float4*)(xs + (size_t)lst[m0 + m] * KK + ks * KH);
                v = src[c];
            }
            *(float4*)&xs_s[m][c * 4] = v;
        }
        __syncthreads();

        // ---- GEMM over K-quarter: packed f32x2 accumulators ----
        unsigned long long acc[TM];
        #pragma unroll
        for (int m = 0; m < TM; m++) acc[m] = 0ull;

        #pragma unroll 2
        for (int k = 0; k < KH; k += 4) {
            const float* wk = Wt + (size_t)k * NN;
            float w0 = wk[0], w1 = wk[NN], w2 = wk[2 * NN], w3 = wk[3 * NN];
            unsigned long long wp0 = pk(w0, w1), wp1 = pk(w2, w3);
            #pragma unroll
            for (int m = 0; m < TM; m++) {
                ulonglong2 xv = *(const ulonglong2*)&xs_s[m][k];  // LDS.128 bcast
                FFMA2(acc[m], xv.x, wp0);
                FFMA2(acc[m], xv.y, wp1);
            }
        }

        // ---- store partials (coalesced) ----
        #pragma unroll
        for (int m = 0; m < TM; m++) {
            if (m >= mc) break;
            g_part[ks][lst[m0 + m]][tid] = fold(acc[m]);
        }
    }
}

// ---------------- stage 2: bias + fused log-softmax + outputs ----------------
#define RW 8
__global__ __launch_bounds__(256, 4)
void softmax_kernel(const int* __restrict__ task_id,
                    const int* __restrict__ action,
                    const float* __restrict__ bias,
                    float* __restrict__ out)
{
    __shared__ float redm[RW][8];
    __shared__ float reda[RW][8];
    __shared__ float redb[RW][8];

    const int tid  = threadIdx.x;           // column n = tid
    const int row0 = blockIdx.x * RW;
    const int lane = tid & 31;
    const int wid  = tid >> 5;

    float v[RW];
    #pragma unroll
    for (int r = 0; r < RW; r++) {
        const int row = row0 + r;
        const int t   = task_id[row];
        v[r] = (g_part[0][row][tid] + g_part[1][row][tid])
             + (g_part[2][row][tid] + g_part[3][row][tid])
             + bias[t * NN + tid];
    }

    // ---- block max per row ----
    float mx[RW];
    #pragma unroll
    for (int r = 0; r < RW; r++) {
        float x = v[r];
        #pragma unroll
        for (int o = 16; o > 0; o >>= 1)
            x = fmaxf(x, __shfl_xor_sync(0xffffffffu, x, o));
        if (lane == 0) redm[r][wid] = x;
    }
    __syncthreads();
    #pragma unroll
    for (int r = 0; r < RW; r++) {
        float x = redm[r][0];
        #pragma unroll
        for (int w = 1; w < 8; w++) x = fmaxf(x, redm[r][w]);
        mx[r] = x;
    }

    // ---- block sums: s1 = sum exp(d), s2 = sum exp(d)*d ----
    #pragma unroll
    for (int r = 0; r < RW; r++) {
        float d = v[r] - mx[r];
        float e = __expf(d);
        float s1 = e, s2 = e * d;
        #pragma unroll
        for (int o = 16; o > 0; o >>= 1) {
            s1 += __shfl_xor_sync(0xffffffffu, s1, o);
            s2 += __shfl_xor_sync(0xffffffffu, s2, o);
        }
        if (lane == 0) { reda[r][wid] = s1; redb[r][wid] = s2; }
    }
    __syncthreads();

    // ---- outputs ----
    #pragma unroll
    for (int r = 0; r < RW; r++) {
        float s1 = 0.f, s2 = 0.f;
        #pragma unroll
        for (int w = 0; w < 8; w++) { s1 += reda[r][w]; s2 += redb[r][w]; }
        const int   row  = row0 + r;
        const int   a    = action[row];
        const float logS = logf(s1);
        if (tid == a)
            out[BB + row] = v[r] - mx[r] - logS;       // log_prob
        if (tid == 0) {
            out[row]          = (float)a;              // action (as float)
            out[2 * BB + row] = logS - s2 / s1;        // entropy
        }
    }
}

extern "C" void kernel_launch(void* const* d_in, const int* in_sizes, int n_in,
                              void* d_out, int out_size) {
    const float* xs      = (const float*)d_in[0];
    const int*   task_id = (const int*)d_in[1];
    const int*   action  = (const int*)d_in[2];
    const float* W       = (const float*)d_in[3];
    const float* bias    = (const float*)d_in[4];
    float*       out     = (float*)d_out;

    setup_kernel<<<TT, 256>>>(task_id);
    dim3 grid(TT, NSLOT, KSPLIT);
    logits_kernel<<<grid, 256>>>(xs, W);
    softmax_kernel<<<BB / RW, 256>>>(task_id, action, bias, out);
}

// round 10
// speedup vs baseline: 1.3414x; 1.3414x over previous
#include <cuda_runtime.h>

// LinearActorNet: B=2048, K=512, N=256, T=64. task_id/action int32.
// out layout (float32): [action(B) | log_prob(B) | entropy(B)]
//
// 3-stage deterministic pipeline (no atomics):
//  1) setup:  64 CTAs x 256 thr, register-cached ballot compaction.
//  2) logits: grid (64 tasks x 4 slots x 4 K-quarters), 256 thr,
//     tile = 16 rows x 256 cols: thread = (row-group rg, col pair cl),
//     8 rows x 2 cols per thread, packed f32x2 FFMA. launch_bounds(256,3)
//     so the 32-reg accumulator file does NOT spill.
//  3) softmax: 256 CTAs x 8 rows; sum 4 partials + bias, fused log-softmax.

#define BB 2048
#define KK 512
#define NN 256
#define TT 64
#define TMR 16              // tile rows
#define NSLOT 4
#define KSPLIT 4
#define KH 128
#define LSTRIDE 128

__device__ unsigned short g_list[TT * LSTRIDE];
__device__ int g_cnt[TT];
__device__ float g_part[KSPLIT][BB][NN];

union f2u { float2 f; unsigned long long u; };
__device__ __forceinline__ unsigned long long pk(float lo, float hi) {
    f2u u; u.f = make_float2(lo, hi); return u.u;
}
__device__ __forceinline__ float fold(unsigned long long v) {
    f2u u; u.u = v; return u.f.x + u.f.y;
}
#define FFMA2(d, a, b) \
    asm("fma.rn.f32x2 %0, %1, %2, %0;" : "+l"(d) : "l"(a), "l"(b))

// ---------------- setup: per-task parallel compaction ----------------
__global__ __launch_bounds__(256, 4)
void setup_kernel(const int* __restrict__ task_id)
{
    const int t    = blockIdx.x;
    const int lane = threadIdx.x & 31;
    const int w    = threadIdx.x >> 5;          // 0..7
    const unsigned lt = (1u << lane) - 1u;
    __shared__ int wcnt[8];

    // hoist all 8 ids into registers (MLP=8, one latency)
    int ids[8];
    #pragma unroll
    for (int i = 0; i < 8; i++)
        ids[i] = task_id[w * 256 + i * 32 + lane];

    int c = 0;
    #pragma unroll
    for (int i = 0; i < 8; i++)
        c += __popc(__ballot_sync(0xffffffffu, ids[i] == t));
    if (lane == 0) wcnt[w] = c;
    __syncthreads();
    int base = 0;
    #pragma unroll
    for (int i = 0; i < 8; i++) if (i < w) base += wcnt[i];
    if (w == 7 && lane == 0) g_cnt[t] = base + wcnt[7];

    #pragma unroll
    for (int i = 0; i < 8; i++) {
        bool p = (ids[i] == t);
        unsigned m = __ballot_sync(0xffffffffu, p);
        if (p) {
            int pos = base + __popc(m & lt);
            if (pos < LSTRIDE)
                g_list[t * LSTRIDE + pos] =
                    (unsigned short)(w * 256 + i * 32 + lane);
        }
        base += __popc(m);
    }
}

// ---------------- stage 1: split-K partial logits ----------------
__global__ __launch_bounds__(256, 3)
void logits_kernel(const float* __restrict__ xs,
                   const float* __restrict__ W)
{
    __shared__ float xs_s[TMR][KH];         // 8 KB

    const int tid  = threadIdx.x;
    const int rg   = tid >> 7;              // row group 0/1 (rows rg*8..rg*8+7)
    const int cl   = tid & 127;             // owns cols cl and cl+128
    const int t    = blockIdx.x;
    const int slot = blockIdx.y;
    const int ks   = blockIdx.z;

    const int cnt = min(g_cnt[t], LSTRIDE);
    if (slot * TMR >= cnt) return;
    const unsigned short* __restrict__ lst = g_list + t * LSTRIDE;

    const float* __restrict__ Wt =
        W + (size_t)t * (KK * NN) + (size_t)ks * KH * NN + cl;

    for (int tile = slot; tile * TMR < cnt; tile += NSLOT) {
        const int m0 = tile * TMR;
        const int mc = min(TMR, cnt - m0);
        __syncthreads();

        // ---- stage xs tile [TMR][KH] (float4, coalesced) ----
        #pragma unroll
        for (int i = 0; i < (TMR * KH / 4) / 256; i++) {   // 2 iters
            int idx = i * 256 + tid;
            int m = idx >> 5;                              // 32 float4 per row
            int c = idx & 31;
            float4 v = make_float4(0.f, 0.f, 0.f, 0.f);
            if (m < mc) {
                const float4* src =
                    (const float4*)(xs + (size_t)lst[m0 + m] * KK + ks * KH);
                v = src[c];
            }
            *(float4*)&xs_s[m][c * 4] = v;
        }
        __syncthreads();

        // ---- GEMM: 8 rows x 2 cols per thread, packed f32x2 ----
        unsigned long long acc0[8], acc1[8];
        #pragma unroll
        for (int m = 0; m < 8; m++) { acc0[m] = 0ull; acc1[m] = 0ull; }

        #pragma unroll 2
        for (int k = 0; k < KH; k += 4) {
            const float* wk = Wt + (size_t)k * NN;
            float a0 = wk[0],   a1 = wk[NN],     a2 = wk[2*NN],     a3 = wk[3*NN];
            float b0 = wk[128], b1 = wk[NN+128], b2 = wk[2*NN+128], b3 = wk[3*NN+128];
            unsigned long long wA0 = pk(a0, a1), wA1 = pk(a2, a3);
            unsigned long long wB0 = pk(b0, b1), wB1 = pk(b2, b3);
            #pragma unroll
            for (int m = 0; m < 8; m++) {
                ulonglong2 xv =
                    *(const ulonglong2*)&xs_s[rg * 8 + m][k];  // LDS.128 bcast
                FFMA2(acc0[m], xv.x, wA0);
                FFMA2(acc0[m], xv.y, wA1);
                FFMA2(acc1[m], xv.x, wB0);
                FFMA2(acc1[m], xv.y, wB1);
            }
        }

        // ---- store partials (coalesced) ----
        #pragma unroll
        for (int m = 0; m < 8; m++) {
            int r = rg * 8 + m;
            if (r < mc) {
                float* dst = &g_part[ks][lst[m0 + r]][0];
                dst[cl]       = fold(acc0[m]);
                dst[cl + 128] = fold(acc1[m]);
            }
        }
    }
}

// ---------------- stage 2: bias + fused log-softmax + outputs ----------------
#define RW 8
__global__ __launch_bounds__(256, 4)
void softmax_kernel(const int* __restrict__ task_id,
                    const int* __restrict__ action,
                    const float* __restrict__ bias,
                    float* __restrict__ out)
{
    __shared__ float redm[RW][8];
    __shared__ float reda[RW][8];
    __shared__ float redb[RW][8];

    const int tid  = threadIdx.x;           // column n = tid
    const int row0 = blockIdx.x * RW;
    const int lane = tid & 31;
    const int wid  = tid >> 5;

    float v[RW];
    #pragma unroll
    for (int r = 0; r < RW; r++) {
        const int row = row0 + r;
        const int t   = task_id[row];
        v[r] = (g_part[0][row][tid] + g_part[1][row][tid])
             + (g_part[2][row][tid] + g_part[3][row][tid])
             + bias[t * NN + tid];
    }

    float mx[RW];
    #pragma unroll
    for (int r = 0; r < RW; r++) {
        float x = v[r];
        #pragma unroll
        for (int o = 16; o > 0; o >>= 1)
            x = fmaxf(x, __shfl_xor_sync(0xffffffffu, x, o));
        if (lane == 0) redm[r][wid] = x;
    }
    __syncthreads();
    #pragma unroll
    for (int r = 0; r < RW; r++) {
        float x = redm[r][0];
        #pragma unroll
        for (int w = 1; w < 8; w++) x = fmaxf(x, redm[r][w]);
        mx[r] = x;
    }

    #pragma unroll
    for (int r = 0; r < RW; r++) {
        float d = v[r] - mx[r];
        float e = __expf(d);
        float s1 = e, s2 = e * d;
        #pragma unroll
        for (int o = 16; o > 0; o >>= 1) {
            s1 += __shfl_xor_sync(0xffffffffu, s1, o);
            s2 += __shfl_xor_sync(0xffffffffu, s2, o);
        }
        if (lane == 0) { reda[r][wid] = s1; redb[r][wid] = s2; }
    }
    __syncthreads();

    #pragma unroll
    for (int r = 0; r < RW; r++) {
        float s1 = 0.f, s2 = 0.f;
        #pragma unroll
        for (int w = 0; w < 8; w++) { s1 += reda[r][w]; s2 += redb[r][w]; }
        const int   row  = row0 + r;
        const int   a    = action[row];
        const float logS = logf(s1);
        if (tid == a)
            out[BB + row] = v[r] - mx[r] - logS;       // log_prob
        if (tid == 0) {
            out[row]          = (float)a;              // action (as float)
            out[2 * BB + row] = logS - s2 / s1;        // entropy
        }
    }
}

extern "C" void kernel_launch(void* const* d_in, const int* in_sizes, int n_in,
                              void* d_out, int out_size) {
    const float* xs      = (const float*)d_in[0];
    const int*   task_id = (const int*)d_in[1];
    const int*   action  = (const int*)d_in[2];
    const float* W       = (const float*)d_in[3];
    const float* bias    = (const float*)d_in[4];
    float*       out     = (float*)d_out;

    setup_kernel<<<TT, 256>>>(task_id);
    dim3 grid(TT, NSLOT, KSPLIT);
    logits_kernel<<<grid, 256>>>(xs, W);
    softmax_kernel<<<BB / RW, 256>>>(task_id, action, bias, out);
}